// round 3
// baseline (speedup 1.0000x reference)
#include <cuda_runtime.h>
#include <math.h>
#include <stdint.h>

#define TT 1024
#define HH 2880
#define II 2880
#define EE 16
#define KTOP 4
#define NROWS (TT * KTOP)
#define ALPHA 1.702f
#define LIMIT 7.0f

// GEMM tiling: BM=128, BN=160, BK=32 floats (128B rows, SW128)
#define BM 128
#define BN 160
#define BK 32
#define NKT (HH / BK)            // 90
#define A_BYTES (BM * BK * 4)    // 16384
#define B_BYTES (BN * BK * 4)    // 20480
#define STAGE_BYTES (A_BYTES + B_BYTES)

// ---------------- scratch -----------------------------------------------
__device__ float g_gate[(size_t)NROWS * II];
__device__ float g_up[(size_t)NROWS * II];
__device__ float g_dn[(size_t)NROWS * HH];
__device__ int   g_offs[EE + 1];
__device__ int   g_pos[NROWS];
__device__ int   g_rowtok[NROWS];
__device__ float g_roww[NROWS];
__device__ int   g_tidx[NROWS];
__device__ float g_tw[NROWS];

// ---------------- helpers -----------------------------------------------
__device__ __forceinline__ unsigned f2tf(float x) {
    unsigned r;
    asm("cvt.rna.tf32.f32 %0, %1;" : "=r"(r) : "f"(x));
    return r;
}
__device__ __forceinline__ uint32_t smem_u32(const void* p) {
    uint32_t a;
    asm("{ .reg .u64 t; cvta.to.shared.u64 t, %1; cvt.u32.u64 %0, t; }" : "=r"(a) : "l"(p));
    return a;
}
__device__ __forceinline__ uint32_t SWZ(uint32_t off) {
    return off ^ ((off >> 3) & 0x70u);
}
#define STS128(addr, a, b, c, d)                                            \
    asm volatile("st.shared.v4.b32 [%0], {%1,%2,%3,%4};" ::"r"(addr),        \
                 "r"(a), "r"(b), "r"(c), "r"(d) : "memory")

__device__ __forceinline__ void ldsm4(unsigned* r, uint32_t addr) {
    asm volatile("ldmatrix.sync.aligned.m8n8.x4.shared.b16 {%0,%1,%2,%3}, [%4];"
                 : "=r"(r[0]), "=r"(r[1]), "=r"(r[2]), "=r"(r[3]) : "r"(addr));
}
__device__ __forceinline__ void ldsm2(unsigned* r, uint32_t addr) {
    asm volatile("ldmatrix.sync.aligned.m8n8.x2.shared.b16 {%0,%1}, [%2];"
                 : "=r"(r[0]), "=r"(r[1]) : "r"(addr));
}
__device__ __forceinline__ void mma8(float* d, const unsigned* a, const unsigned* b) {
    asm volatile(
        "mma.sync.aligned.m16n8k8.row.col.f32.tf32.tf32.f32 "
        "{%0,%1,%2,%3}, {%4,%5,%6,%7}, {%8,%9}, {%0,%1,%2,%3};"
        : "+f"(d[0]), "+f"(d[1]), "+f"(d[2]), "+f"(d[3])
        : "r"(a[0]), "r"(a[1]), "r"(a[2]), "r"(a[3]), "r"(b[0]), "r"(b[1]));
}

// ---------------- router ------------------------------------------------
__global__ void router_kernel(const float* __restrict__ x,
                              const float* __restrict__ rw,
                              const float* __restrict__ rb) {
    int t = blockIdx.x;
    int tid = threadIdx.x;
    float acc[EE];
#pragma unroll
    for (int e = 0; e < EE; e++) acc[e] = 0.f;
    const float* xr = x + (size_t)t * HH;
    for (int h = tid; h < HH; h += 128) {
        float xv = xr[h];
#pragma unroll
        for (int e = 0; e < EE; e++) acc[e] = fmaf(xv, rw[e * HH + h], acc[e]);
    }
#pragma unroll
    for (int e = 0; e < EE; e++) {
#pragma unroll
        for (int o = 16; o > 0; o >>= 1) acc[e] += __shfl_xor_sync(0xffffffffu, acc[e], o);
    }
    __shared__ float sl[4][EE];
    int w = tid >> 5;
    if ((tid & 31) == 0) {
#pragma unroll
        for (int e = 0; e < EE; e++) sl[w][e] = acc[e];
    }
    __syncthreads();
    if (tid == 0) {
        float lg[EE];
        float mx = -1e30f;
#pragma unroll
        for (int e = 0; e < EE; e++) {
            lg[e] = sl[0][e] + sl[1][e] + sl[2][e] + sl[3][e] + rb[e];
            mx = fmaxf(mx, lg[e]);
        }
        float p[EE];
#pragma unroll
        for (int e = 0; e < EE; e++) p[e] = __expf(lg[e] - mx);
        bool used[EE];
#pragma unroll
        for (int e = 0; e < EE; e++) used[e] = false;
        int sel[KTOP]; float pv[KTOP]; float psum = 0.f;
        for (int k = 0; k < KTOP; k++) {
            int best = 0; float bv = -1.f;
            for (int e = 0; e < EE; e++)
                if (!used[e] && p[e] > bv) { bv = p[e]; best = e; }
            used[best] = true; sel[k] = best; pv[k] = bv; psum += bv;
        }
        float inv = 1.f / psum;
        for (int k = 0; k < KTOP; k++) {
            g_tidx[t * 4 + k] = sel[k];
            g_tw[t * 4 + k]   = pv[k] * inv;
        }
    }
}

// ---------------- deterministic grouping --------------------------------
__global__ void group_kernel() {
    __shared__ unsigned char eid[NROWS];
    __shared__ int base[EE];
    int tid = threadIdx.x;
    for (int i = tid; i < NROWS; i += blockDim.x) eid[i] = (unsigned char)g_tidx[i];
    __syncthreads();
    if (tid == 0) {
        int cnt[EE];
        for (int e = 0; e < EE; e++) cnt[e] = 0;
        for (int i = 0; i < NROWS; i++) cnt[eid[i]]++;
        int s = 0;
        for (int e = 0; e < EE; e++) { base[e] = s; g_offs[e] = s; s += cnt[e]; }
        g_offs[EE] = s;
    }
    __syncthreads();
    if (tid < EE) {
        int cur = base[tid];
        for (int i = 0; i < NROWS; i++) {
            if (eid[i] == (unsigned char)tid) {
                g_pos[i] = cur;
                g_rowtok[cur] = i >> 2;
                g_roww[cur] = g_tw[i];
                cur++;
            }
        }
    }
}

// ---------------- grouped GEMM: ldmatrix + tf32 mma, double buffered -----
// MODE 0: gate = gather(x) @ w1^T + b1  -> g_gate
// MODE 1: up   = gather(x) @ w3^T + b3  -> g_up
// MODE 2: dn   = w * (h @ w2^T + b2)    -> g_dn  (h in g_gate)
template<int MODE>
__global__ __launch_bounds__(256)
void moe_gemm(const float* __restrict__ Xin, const float* __restrict__ W,
              const float* __restrict__ Bias) {
    const int e = blockIdx.z;
    const int gbase = g_offs[e];
    const int Me = g_offs[e + 1] - gbase;
    const int m0 = blockIdx.y * BM;
    if (m0 >= Me) return;
    const int n0 = blockIdx.x * BN;

    const float* X = (MODE == 2) ? (const float*)g_gate : Xin;

    extern __shared__ char smraw[];
    uint32_t sbase = smem_u32(smraw);          // 1024-aligned (dynamic smem)
    const int tid = threadIdx.x;
    const int lane = tid & 31;
    const int warp = tid >> 5;
    const int wm = warp >> 2;                  // 0..1
    const int wn = warp & 3;                   // 0..3

    float acc[4][5][4];
#pragma unroll
    for (int i = 0; i < 4; i++)
#pragma unroll
        for (int j = 0; j < 5; j++)
#pragma unroll
            for (int q = 0; q < 4; q++) acc[i][j][q] = 0.f;

    // ---- staging coordinates (per thread, fixed across K) ----
    const float* ga[4]; uint32_t sa[4]; bool va[4];
#pragma unroll
    for (int j = 0; j < 4; j++) {
        int f4 = tid + j * 256;
        int row = f4 >> 3, c4 = f4 & 7;
        va[j] = (m0 + row) < Me;
        sa[j] = SWZ((uint32_t)(row * 128 + c4 * 16));
        if (va[j]) {
            if (MODE == 2) ga[j] = X + (size_t)(gbase + m0 + row) * II + c4 * 4;
            else           ga[j] = X + (size_t)g_rowtok[gbase + m0 + row] * HH + c4 * 4;
        } else ga[j] = X;
    }
    const float* gb[5]; uint32_t sbo[5];
#pragma unroll
    for (int j = 0; j < 5; j++) {
        int f4 = tid + j * 256;
        int row = f4 >> 3, c4 = f4 & 7;
        sbo[j] = SWZ((uint32_t)(row * 128 + c4 * 16));
        gb[j] = W + (size_t)e * HH * II + (size_t)(n0 + row) * HH + c4 * 4;
    }

    // ---- ldmatrix lane constants ----
    const int at = lane >> 3;                        // A tile index 0..3
    const int arow = wm * 64 + (at & 1) * 8 + (lane & 7);   // + mt*16
    const int acol = (at >> 1) * 16;                 // byte offset within row
    const int bt = lane >> 3;
    const int brow = wn * 40 + (bt >> 1) * 8 + (lane & 7);  // + jpair*16
    const int bcol = (bt & 1) * 16;
    const int brow2 = wn * 40 + 32 + (lane & 7);     // nt=4 tile (x2)
    const int bcol2 = ((lane >> 3) & 1) * 16;

    // ---- prefetch kt=0 ----
    float4 ra[4], rb[5];
#pragma unroll
    for (int j = 0; j < 4; j++)
        ra[j] = va[j] ? *(const float4*)(ga[j]) : make_float4(0.f, 0.f, 0.f, 0.f);
#pragma unroll
    for (int j = 0; j < 5; j++) rb[j] = *(const float4*)(gb[j]);

#pragma unroll 1
    for (int kt = 0; kt < NKT; ++kt) {
        uint32_t abase = sbase + (kt & 1) * STAGE_BYTES;
        uint32_t bbase = abase + A_BYTES;
        // stage current regs -> smem (tf32-rounded)
#pragma unroll
        for (int j = 0; j < 4; j++)
            STS128(abase + sa[j], f2tf(ra[j].x), f2tf(ra[j].y), f2tf(ra[j].z), f2tf(ra[j].w));
#pragma unroll
        for (int j = 0; j < 5; j++)
            STS128(bbase + sbo[j], f2tf(rb[j].x), f2tf(rb[j].y), f2tf(rb[j].z), f2tf(rb[j].w));
        __syncthreads();
        // prefetch next tile
        if (kt + 1 < NKT) {
            int k0 = (kt + 1) * BK;
#pragma unroll
            for (int j = 0; j < 4; j++)
                if (va[j]) ra[j] = *(const float4*)(ga[j] + k0);
#pragma unroll
            for (int j = 0; j < 5; j++) rb[j] = *(const float4*)(gb[j] + k0);
        }
        // compute on current stage
#pragma unroll
        for (int kk = 0; kk < 32; kk += 8) {
            unsigned af[4][4];
#pragma unroll
            for (int mt = 0; mt < 4; mt++)
                ldsm4(af[mt], abase + SWZ((uint32_t)((arow + mt * 16) * 128 + kk * 4 + acol)));
            unsigned bf[5][2];
            ldsm4(&bf[0][0], bbase + SWZ((uint32_t)(brow * 128 + kk * 4 + bcol)));
            ldsm4(&bf[2][0], bbase + SWZ((uint32_t)((brow + 16) * 128 + kk * 4 + bcol)));
            ldsm2(&bf[4][0], bbase + SWZ((uint32_t)(brow2 * 128 + kk * 4 + bcol2)));
#pragma unroll
            for (int mt = 0; mt < 4; mt++)
#pragma unroll
                for (int nt = 0; nt < 5; nt++)
                    mma8(acc[mt][nt], af[mt], bf[nt]);
        }
        __syncthreads();
    }

    // ---- epilogue ----
#pragma unroll
    for (int mt = 0; mt < 4; mt++) {
        int rloc0 = wm * 64 + mt * 16 + (lane >> 2);
#pragma unroll
        for (int half = 0; half < 2; half++) {
            int r = m0 + rloc0 + half * 8;
            if (r >= Me) continue;
            size_t orow = (size_t)(gbase + r) * (size_t)((MODE == 2) ? HH : II);
            float* Out = (MODE == 0) ? g_gate : (MODE == 1) ? g_up : g_dn;
            float wgt = (MODE == 2) ? g_roww[gbase + r] : 1.f;
#pragma unroll
            for (int nt = 0; nt < 5; nt++) {
                int col = n0 + wn * 40 + nt * 8 + (lane & 3) * 2;
                float v0 = acc[mt][nt][half * 2 + 0] + Bias[e * HH + col];
                float v1 = acc[mt][nt][half * 2 + 1] + Bias[e * HH + col + 1];
                if (MODE == 2) { v0 *= wgt; v1 *= wgt; }
                Out[orow + col]     = v0;
                Out[orow + col + 1] = v1;
            }
        }
    }
}

// ---------------- clipped SwiGLU ----------------------------------------
__global__ void act_kernel() {
    size_t idx = ((size_t)blockIdx.x * 256 + threadIdx.x) * 4;
    float4 g = *(const float4*)&g_gate[idx];
    float4 u = *(const float4*)&g_up[idx];
    float gv[4] = {g.x, g.y, g.z, g.w};
    float uv[4] = {u.x, u.y, u.z, u.w};
    float r[4];
#pragma unroll
    for (int i = 0; i < 4; i++) {
        float gg = fminf(gv[i], LIMIT);
        float uu = fminf(fmaxf(uv[i], -LIMIT), LIMIT);
        float s = 1.f / (1.f + __expf(-ALPHA * gg));
        r[i] = (uu + 1.f) * (gg * s);
    }
    *(float4*)&g_gate[idx] = make_float4(r[0], r[1], r[2], r[3]);
}

// ---------------- per-token fixed-order combine -------------------------
__global__ void combine_kernel(float* __restrict__ y) {
    int t = blockIdx.x;
    const float* r0 = g_dn + (size_t)g_pos[t * 4 + 0] * HH;
    const float* r1 = g_dn + (size_t)g_pos[t * 4 + 1] * HH;
    const float* r2 = g_dn + (size_t)g_pos[t * 4 + 2] * HH;
    const float* r3 = g_dn + (size_t)g_pos[t * 4 + 3] * HH;
    float* yo = y + (size_t)t * HH;
    for (int c = threadIdx.x * 4; c < HH; c += 256 * 4) {
        float4 a = *(const float4*)(r0 + c);
        float4 b = *(const float4*)(r1 + c);
        float4 d = *(const float4*)(r2 + c);
        float4 f = *(const float4*)(r3 + c);
        *(float4*)(yo + c) = make_float4(a.x + b.x + d.x + f.x, a.y + b.y + d.y + f.y,
                                         a.z + b.z + d.z + f.z, a.w + b.w + d.w + f.w);
    }
}

// ---------------- launch ------------------------------------------------
extern "C" void kernel_launch(void* const* d_in, const int* in_sizes, int n_in,
                              void* d_out, int out_size) {
    const float* x  = (const float*)d_in[0];
    const float* rw = (const float*)d_in[1];
    const float* rb = (const float*)d_in[2];
    const float* w1 = (const float*)d_in[3];
    const float* b1 = (const float*)d_in[4];
    const float* w3 = (const float*)d_in[5];
    const float* b3 = (const float*)d_in[6];
    const float* w2 = (const float*)d_in[7];
    const float* b2 = (const float*)d_in[8];
    float* y = (float*)d_out;

    const int smem = 2 * STAGE_BYTES;   // 73728
    cudaFuncSetAttribute(moe_gemm<0>, cudaFuncAttributeMaxDynamicSharedMemorySize, smem);
    cudaFuncSetAttribute(moe_gemm<1>, cudaFuncAttributeMaxDynamicSharedMemorySize, smem);
    cudaFuncSetAttribute(moe_gemm<2>, cudaFuncAttributeMaxDynamicSharedMemorySize, smem);

    router_kernel<<<TT, 128>>>(x, rw, rb);
    group_kernel<<<1, 256>>>();

    dim3 ggrid(HH / BN, 8, EE);   // (18, 8, 16)
    moe_gemm<0><<<ggrid, 256, smem>>>(x, w1, b1);
    moe_gemm<1><<<ggrid, 256, smem>>>(x, w3, b3);

    act_kernel<<<(NROWS * II) / (256 * 4), 256>>>();

    moe_gemm<2><<<ggrid, 256, smem>>>(nullptr, w2, b2);

    combine_kernel<<<TT, 256>>>(y);
}